// round 11
// baseline (speedup 1.0000x reference)
#include <cuda_runtime.h>
#include <cuda_bf16.h>
#include <cstdint>

#define BATCH 2
#define NANCH 261888
#define PRE_NMS 6000
#define PRE2 1280          // prefix length for fast-path NMS
#define NW2 (PRE2 / 64)    // 20 words per prefix row
#define PROP 1000
#define NMS_THR 0.7f
#define NBINS 2048
#define SCAP 12288
#define BUCKET_CAP 2048
#define SB_GRID 128

#define HS_BLOCKS 128
#define HS_THREADS 1024
#define HS_PER_THREAD 2    // float4s per thread: 128*1024*2 = 262144 >= 261888

typedef unsigned long long u64;

// ---------------- scratch (zero at module load; re-zeroed by tail kernel) -------
__device__ int g_hist[BATCH * NBINS];
__device__ int g_offset[BATCH * NBINS];
__device__ int g_binfill[BATCH * NBINS];
__device__ int g_cutbin[BATCH];
__device__ unsigned int g_ticket;
__device__ int g_ready;
__device__ u64 g_sorted[BATCH * SCAP];
__device__ float4 g_boxes[BATCH * PRE_NMS];
__device__ u64 g_mask2[(size_t)BATCH * PRE2 * NW2];   // 400 KB prefix mask

// ---------------- helpers ----------------
__device__ __forceinline__ int score_bin(float s) {
    int b = (int)(s * (float)NBINS);
    if (b < 0) b = 0;
    if (b > NBINS - 1) b = NBINS - 1;
    return b;
}

// keep ⟺ iou > THR ⟺ (1+THR)*inter > THR*(areaR+areaC+eps)  (denominator > 0)
__device__ __forceinline__ bool iou_gt(float4 a, float aR7, float4 c, float cA7) {
    float ih = fmaxf(fminf(a.z, c.z) - fmaxf(a.x, c.x), 0.f);
    float iw = fmaxf(fminf(a.w, c.w) - fmaxf(a.y, c.y), 0.f);
    float inter = ih * iw;
    return 1.7f * inter > aR7 + cA7;
}

// ------ 1: fused histogram + suffix-scan + scatter (single read of cls) --------
__global__ void __launch_bounds__(HS_THREADS, 1)
histscatter_kernel(const float4* __restrict__ cls4) {
    __shared__ int h[BATCH * NBINS];   // 16 KB
    for (int t = threadIdx.x; t < BATCH * NBINS; t += HS_THREADS) h[t] = 0;
    __syncthreads();
    const int total4 = BATCH * NANCH / 2;   // 261888
    const int half = NANCH / 2;
    const int gsz = HS_BLOCKS * HS_THREADS; // 131072
    int tid = blockIdx.x * HS_THREADS + threadIdx.x;

    float sc[HS_PER_THREAD * 2];
#pragma unroll
    for (int u = 0; u < HS_PER_THREAD; ++u) {
        int t = tid + u * gsz;
        float y = -1.f, w = -1.f;
        if (t < total4) {
            float4 v = cls4[t];
            y = v.y; w = v.w;
            int b = t / half;
            atomicAdd(&h[b * NBINS + score_bin(y)], 1);
            atomicAdd(&h[b * NBINS + score_bin(w)], 1);
        }
        sc[u * 2 + 0] = y;
        sc[u * 2 + 1] = w;
    }
    __syncthreads();
    for (int t = threadIdx.x; t < BATCH * NBINS; t += HS_THREADS)
        if (h[t]) atomicAdd(&g_hist[t], h[t]);

    __threadfence();
    __shared__ int is_last;
    if (threadIdx.x == 0)
        is_last = (atomicAdd(&g_ticket, 1u) == HS_BLOCKS - 1) ? 1 : 0;
    __syncthreads();

    if (is_last) {
        __shared__ int sA[1024], sB[1024];
        for (int b = 0; b < BATCH; ++b) {
            int t = threadIdx.x;
            int base = b * NBINS + t * 2;
            int h0 = g_hist[base + 0], h1 = g_hist[base + 1];
            int sum = h0 + h1;
            sA[t] = sum;
            __syncthreads();
            int* src = sA; int* dst = sB;
            for (int d = 1; d < 1024; d <<= 1) {
                int v = src[t];
                if (t + d < 1024) v += src[t + d];
                dst[t] = v;
                __syncthreads();
                int* tmp = src; src = dst; dst = tmp;
            }
            int excl = src[t] - sum;
            int off1 = excl;
            int off0 = off1 + h1;
            g_offset[base + 0] = off0; g_offset[base + 1] = off1;
            if (off1 + h1 >= PRE_NMS) atomicMax(&g_cutbin[b], t * 2 + 1);
            else if (off0 + h0 >= PRE_NMS) atomicMax(&g_cutbin[b], t * 2 + 0);
            __syncthreads();
        }
        __threadfence();
        if (threadIdx.x == 0) atomicExch(&g_ready, 1);
    }

    if (threadIdx.x == 0) {
        while (atomicAdd(&g_ready, 0) == 0) __nanosleep(128);
    }
    __syncthreads();
    __threadfence();

    int cut0 = g_cutbin[0];
    int cut1 = g_cutbin[1];
#pragma unroll
    for (int u = 0; u < HS_PER_THREAD; ++u) {
        int t = tid + u * gsz;
        if (t >= total4) continue;
        int b = t / half;
        int i0 = (t - b * half) * 2;
        int cut = (b == 0) ? cut0 : cut1;
#pragma unroll
        for (int e = 0; e < 2; ++e) {
            float s = sc[u * 2 + e];
            int i = i0 + e;
            int q = score_bin(s);
            if (q >= cut) {
                int pos = g_offset[b * NBINS + q] + atomicAdd(&g_binfill[b * NBINS + q], 1);
                if (pos < SCAP) {
                    unsigned int sb = __float_as_uint(s);
                    g_sorted[b * SCAP + pos] =
                        ((u64)sb << 32) | (u64)(0xFFFFFFFFu - (unsigned)i);
                }
            }
        }
    }
}

// ---------------- 2: per-bucket sort + box decode (cutbin-relative grid) -------
__global__ void sortbox_kernel(const float* __restrict__ rpn_bbox,
                               const float* __restrict__ anchors) {
    int b = blockIdx.y;
    int cut = g_cutbin[b];
    __shared__ u64 s[BUCKET_CAP];
    for (int bin = cut + blockIdx.x; bin < NBINS; bin += SB_GRID) {
        int cnt = g_hist[b * NBINS + bin];
        if (cnt <= 0) continue;
        if (cnt > BUCKET_CAP) cnt = BUCKET_CAP;
        int off = g_offset[b * NBINS + bin];
        if (off >= PRE_NMS) continue;
        int P = 1;
        while (P < cnt) P <<= 1;
        const u64* src = g_sorted + (size_t)b * SCAP + off;
        for (int t = threadIdx.x; t < P; t += blockDim.x)
            s[t] = (t < cnt) ? src[t] : 0ULL;
        __syncthreads();
        if (cnt > 1) {
            for (int k = 2; k <= P; k <<= 1) {
                for (int j = k >> 1; j > 0; j >>= 1) {
                    for (int i = threadIdx.x; i < P; i += blockDim.x) {
                        int ixj = i ^ j;
                        if (ixj > i) {
                            bool dir = ((i & k) == 0);
                            u64 a = s[i], c = s[ixj];
                            if ((a < c) == dir) { s[i] = c; s[ixj] = a; }
                        }
                    }
                    __syncthreads();
                }
            }
        }
        for (int t = threadIdx.x; t < cnt; t += blockDim.x) {
            int rank = off + t;
            if (rank >= PRE_NMS) continue;
            unsigned int low = (unsigned int)(s[t] & 0xFFFFFFFFu);
            int idx = (int)(0xFFFFFFFFu - low);
            size_t base = ((size_t)b * NANCH + (size_t)idx) * 4;
            float a0 = anchors[base + 0], a1 = anchors[base + 1];
            float a2 = anchors[base + 2], a3 = anchors[base + 3];
            float d0 = rpn_bbox[base + 0] * 0.1f;
            float d1 = rpn_bbox[base + 1] * 0.1f;
            float d2 = rpn_bbox[base + 2] * 0.2f;
            float d3 = rpn_bbox[base + 3] * 0.2f;
            float h = a2 - a0, w = a3 - a1;
            float cy = a0 + 0.5f * h + d0 * h;
            float cx = a1 + 0.5f * w + d1 * w;
            h = h * expf(d2);
            w = w * expf(d3);
            float y1 = cy - 0.5f * h;
            float x1 = cx - 0.5f * w;
            float y2 = y1 + h;
            float x2 = x1 + w;
            y1 = fminf(fmaxf(y1, 0.f), 1.f);
            x1 = fminf(fmaxf(x1, 0.f), 1.f);
            y2 = fminf(fmaxf(y2, 0.f), 1.f);
            x2 = fminf(fmaxf(x2, 0.f), 1.f);
            g_boxes[b * PRE_NMS + rank] = make_float4(y1, x1, y2, x2);
        }
        __syncthreads();
    }
}

// -------- 3: prefix IoU bitmask (LOWER triangle: row i needs cols <= wi) -------
__global__ void __launch_bounds__(128) maskpre_kernel() {
    int b = blockIdx.z;
    int row0 = blockIdx.y * 128;
    int col0 = blockIdx.x * 64;
    if (col0 >= row0 + 128) return;   // no column <= any row-word in block
    __shared__ float4 cbox[64];
    __shared__ float cA7[64];
    int t = threadIdx.x;              // 128 threads
    if (t < 64) {
        float4 cb = g_boxes[b * PRE_NMS + col0 + t];
        cbox[t] = cb;
        cA7[t] = 0.7f * ((cb.z - cb.x) * (cb.w - cb.y) + 1e-8f);
    }
    __syncthreads();
    int r = row0 + t;
    float4 rb = g_boxes[b * PRE_NMS + r];
    float aR7 = 0.7f * ((rb.z - rb.x) * (rb.w - rb.y));
    unsigned lo = 0, hi = 0;
#pragma unroll
    for (int jj = 0; jj < 32; ++jj)
        if (iou_gt(rb, aR7, cbox[jj], cA7[jj])) lo |= (1u << jj);
#pragma unroll
    for (int jj = 0; jj < 32; ++jj)
        if (iou_gt(rb, aR7, cbox[32 + jj], cA7[32 + jj])) hi |= (1u << jj);
    g_mask2[((size_t)b * PRE2 + r) * NW2 + blockIdx.x] = ((u64)hi << 32) | lo;
}

// ---- 4: NMS — one-pass forward substitution over word-columns (exact) --------
__global__ void __launch_bounds__(256) nms_kernel(float* __restrict__ out) {
    if (blockIdx.x >= BATCH) {
        // cleanup blocks: re-zero scratch for the next graph replay
        int start = (blockIdx.x - BATCH) * blockDim.x + threadIdx.x;
        for (int t = start; t < BATCH * NBINS; t += 8 * blockDim.x) {
            g_hist[t] = 0;
            g_binfill[t] = 0;
        }
        if (start == 0) {
            g_cutbin[0] = 0; g_cutbin[1] = 0;
            g_ticket = 0u;
            g_ready = 0;
        }
        return;
    }
    int b = blockIdx.x;
    __shared__ u64 keptW[NW2];
    __shared__ u64 dw[64];
    __shared__ u64 spart[256];
    __shared__ u64 s_keptm;
    __shared__ unsigned ball[2];
    __shared__ int list[PROP];
    const u64* M = g_mask2 + (size_t)b * PRE2 * NW2;
    int tid = threadIdx.x;
    int row = tid & 63;       // row within current word-column
    int part = tid >> 6;      // 0..3 word partition
    int kc = 0;

    for (int k = 0; k < NW2; ++k) {
        const u64* rp = M + (size_t)(k * 64 + row) * NW2;
        // external suppression from finalized columns (parallel, 4 parts/row)
        u64 s = 0;
        for (int w = part; w < k; w += 4) s |= rp[w] & keptW[w];
        spart[tid] = s;
        if (part == 0) dw[row] = rp[k];   // diagonal word prefetch
        __syncthreads();
        if (tid < 64) {
            u64 sfull = spart[row] | spart[64 + row] | spart[128 + row] | spart[192 + row];
            unsigned bal = __ballot_sync(0xffffffffu, sfull != 0ULL);
            if ((tid & 31) == 0) ball[tid >> 5] = bal;
        }
        __syncthreads();
        if (tid == 0) {
            u64 supm = ((u64)ball[1] << 32) | (u64)ball[0];
            u64 keptm0 = ~supm;
            // verify: any kept-kept suppression inside the 64x64 diagonal?
            u64 acc = 0;
#pragma unroll
            for (int t = 1; t < 64; ++t) {
                u64 m = 0ULL - ((keptm0 >> t) & 1ULL);
                acc |= dw[t] & keptm0 & ((1ULL << t) - 1ULL) & m;
            }
            u64 keptm;
            if (acc == 0ULL) {
                keptm = keptm0;          // speculation exact
            } else {
                // rare: serial greedy within the column
                keptm = 0;
                for (int t = 0; t < 64; ++t) {
                    if (!((supm >> t) & 1ULL) && ((dw[t] & keptm) == 0ULL))
                        keptm |= (1ULL << t);
                }
            }
            // trim to first (PROP - kc) kept rows
            int pc = __popcll(keptm);
            int rema = PROP - kc;
            while (pc > rema) {
                keptm &= ~(1ULL << (63 - __clzll(keptm)));
                --pc;
            }
            keptW[k] = keptm;
            s_keptm = keptm;
        }
        __syncthreads();
        u64 keptm = s_keptm;
        if (tid < 64 && ((keptm >> tid) & 1ULL)) {
            int pos = kc + __popcll(keptm & ((1ULL << tid) - 1ULL));
            list[pos] = k * 64 + tid;
        }
        kc += __popcll(keptm);
        if (kc >= PROP) break;
    }
    __syncthreads();

    const float4* bx = g_boxes + b * PRE_NMS;
    float4* o = (float4*)(out + (size_t)b * PROP * 4);
    if (kc >= PROP) {
        for (int r = threadIdx.x; r < PROP; r += blockDim.x) o[r] = bx[list[r]];
        return;
    }

    // fallback: exact direct sequential NMS over all 6000 boxes (rarely taken)
    __shared__ float4 kept[PROP];
    __shared__ float keptA7[PROP];
    int kk = 0;
    for (int i = 0; i < PRE_NMS && kk < PROP; ++i) {
        float4 bi = bx[i];
        float aR7 = 0.7f * ((bi.z - bi.x) * (bi.w - bi.y));
        int sup = 0;
        for (int j = threadIdx.x; j < kk; j += blockDim.x)
            if (iou_gt(bi, aR7, kept[j], keptA7[j])) sup = 1;
        sup = __syncthreads_or(sup);
        if (!sup) {
            if (threadIdx.x == 0) {
                kept[kk] = bi;
                keptA7[kk] = 0.7f * ((bi.z - bi.x) * (bi.w - bi.y) + 1e-8f);
            }
            kk++;
            __syncthreads();
        }
    }
    for (int r = threadIdx.x; r < PROP; r += blockDim.x) {
        float4 v = make_float4(0.f, 0.f, 0.f, 0.f);
        if (r < kk) v = kept[r];
        o[r] = v;
    }
}

// ---------------- launch ----------------
extern "C" void kernel_launch(void* const* d_in, const int* in_sizes, int n_in,
                              void* d_out, int out_size) {
    (void)in_sizes; (void)n_in; (void)out_size;
    const float4* cls4 = (const float4*)d_in[0];
    const float* rpn_bbox = (const float*)d_in[1];
    const float* anchors = (const float*)d_in[2];
    float* out = (float*)d_out;

    histscatter_kernel<<<HS_BLOCKS, HS_THREADS>>>(cls4);
    {
        dim3 grid(SB_GRID, BATCH);
        sortbox_kernel<<<grid, 128>>>(rpn_bbox, anchors);
    }
    {
        dim3 grid(NW2, PRE2 / 128, BATCH);   // (20, 10, 2)
        maskpre_kernel<<<grid, 128>>>();
    }
    nms_kernel<<<BATCH + 8, 256>>>(out);
}